// round 1
// baseline (speedup 1.0000x reference)
#include <cuda_runtime.h>

// Problem constants
#define Bd 4
#define Yd 64
#define Xd 64
#define Cd 256
#define Hd 8
#define Fd 32
#define NPIX (Bd*Yd*Xd)   // 16384

// Scratch (static device allocations are allowed)
__device__ float g_Q[NPIX*Cd];
__device__ float g_K[NPIX*Cd];
__device__ float g_V[NPIX*Cd];
__device__ float g_att[NPIX*Cd];

// ---------------------------------------------------------------------------
// SGEMM: C[M x 256] = A[M x 256] @ B[256 x 256], optional pos-emb epilogue (Q)
// BM=128, BN=64, BK=16, 256 threads, 8x4 per thread
// ---------------------------------------------------------------------------
#define GBM 128
#define GBN 64
#define GBK 16

__device__ __forceinline__ void sgemm_256(const float* __restrict__ A,
                                          const float* __restrict__ B,
                                          float* __restrict__ C,
                                          const float* __restrict__ pos,
                                          bool addpos)
{
    __shared__ float As[GBK][GBM + 1];
    __shared__ float Bs[GBK][GBN];
    const int t   = threadIdx.x;
    const int m0  = blockIdx.y * GBM;
    const int n0  = blockIdx.x * GBN;
    const int tm0 = (t >> 4) << 3;   // 0..120 step 8
    const int tn0 = (t & 15) << 2;   // 0..60  step 4

    float acc[8][4];
#pragma unroll
    for (int i = 0; i < 8; i++)
#pragma unroll
        for (int j = 0; j < 4; j++) acc[i][j] = 0.f;

    for (int k0 = 0; k0 < 256; k0 += GBK) {
        // Load A tile (128x16) -> As transposed
#pragma unroll
        for (int i = 0; i < 2; i++) {
            int id  = i * 256 + t;
            int row = id >> 2;          // 0..127
            int c4  = (id & 3) << 2;    // 0,4,8,12
            const float4 v = *(const float4*)(A + (size_t)(m0 + row) * 256 + k0 + c4);
            As[c4 + 0][row] = v.x;
            As[c4 + 1][row] = v.y;
            As[c4 + 2][row] = v.z;
            As[c4 + 3][row] = v.w;
        }
        // Load B tile (16x64)
        {
            int row = t >> 4;           // 0..15
            int c4  = (t & 15) << 2;    // 0..60
            *(float4*)(&Bs[row][c4]) = *(const float4*)(B + (size_t)(k0 + row) * 256 + n0 + c4);
        }
        __syncthreads();
#pragma unroll
        for (int k = 0; k < GBK; k++) {
            float a[8], bb[4];
#pragma unroll
            for (int i = 0; i < 8; i++) a[i] = As[k][tm0 + i];
#pragma unroll
            for (int j = 0; j < 4; j++) bb[j] = Bs[k][tn0 + j];
#pragma unroll
            for (int i = 0; i < 8; i++)
#pragma unroll
                for (int j = 0; j < 4; j++) acc[i][j] = fmaf(a[i], bb[j], acc[i][j]);
        }
        __syncthreads();
    }

#pragma unroll
    for (int i = 0; i < 8; i++) {
        int m = m0 + tm0 + i;
        float4 v = make_float4(acc[i][0], acc[i][1], acc[i][2], acc[i][3]);
        if (addpos) {
            int y  = (m >> 6) & 63;
            int x  = m & 63;
            int qy = y - min(max(y, 3), 60) + 3;
            int qx = x - min(max(x, 3), 60) + 3;
            const float4 pe = *(const float4*)(pos + (size_t)(qy * 7 + qx) * 256 + n0 + tn0);
            v.x += pe.x; v.y += pe.y; v.z += pe.z; v.w += pe.w;
        }
        *(float4*)(C + (size_t)m * 256 + n0 + tn0) = v;
    }
}

__global__ __launch_bounds__(256) void qkv_kernel(const float* __restrict__ X,
                                                  const float* __restrict__ Wq,
                                                  const float* __restrict__ Wk,
                                                  const float* __restrict__ Wv,
                                                  const float* __restrict__ pos)
{
    int mat = blockIdx.z;
    const float* W = (mat == 0) ? Wq : ((mat == 1) ? Wk : Wv);
    float* O       = (mat == 0) ? g_Q : ((mat == 1) ? g_K : g_V);
    sgemm_256(X, W, O, pos, mat == 0);
}

__global__ __launch_bounds__(256) void out_kernel(const float* __restrict__ Wo,
                                                  float* __restrict__ out)
{
    sgemm_256(g_att, Wo, out, nullptr, false);
}

// ---------------------------------------------------------------------------
// Attention: one block per (8x8 pixel tile, head, batch).
// Smem holds the 14x14 halo of K and V (per head) + 49x32 pos_emb slice.
// Warp w handles pixels w, w+8, ... ; lane = feature f. Scores via shfl reduce.
// ---------------------------------------------------------------------------
#define TS   8
#define HALO 14
#define NP   (HALO*HALO)   // 196

__global__ __launch_bounds__(256) void attn_kernel(const float* __restrict__ pos)
{
    extern __shared__ float sm[];
    float* Ks = sm;                 // NP*32
    float* Vs = sm + NP * 32;       // NP*32
    float* Ps = sm + 2 * NP * 32;   // 49*32

    const int tile = blockIdx.x;    // 0..63
    const int h    = blockIdx.y;    // 0..7
    const int b    = blockIdx.z;    // 0..3
    const int Ty   = (tile >> 3) * TS;
    const int Tx   = (tile & 7) * TS;
    const int t    = threadIdx.x;
    const int lane = t & 31;
    const int warp = t >> 5;
    const int hb   = h * 32;

    // Load K/V halo (196 positions x 32 floats, as float4)
    for (int i = t; i < NP * 8; i += 256) {
        int p  = i >> 3;
        int q4 = (i & 7) << 2;
        int ry = p / HALO, rx = p - ry * HALO;
        int gy = min(max(Ty - 3 + ry, 0), 63);
        int gx = min(max(Tx - 3 + rx, 0), 63);
        size_t off = ((size_t)((b * 64 + gy) * 64 + gx)) * 256 + hb + q4;
        *(float4*)(Ks + p * 32 + q4) = *(const float4*)(g_K + off);
        *(float4*)(Vs + p * 32 + q4) = *(const float4*)(g_V + off);
    }
    // Load pos_emb slice for this head (49 x 32)
    for (int i = t; i < 49 * 8; i += 256) {
        int s  = i >> 3;
        int q4 = (i & 7) << 2;
        *(float4*)(Ps + s * 32 + q4) = *(const float4*)(pos + (size_t)s * 256 + hb + q4);
    }
    __syncthreads();

    const float scale = 0.17677669529663687f; // 1/sqrt(32)

    for (int pi = warp; pi < 64; pi += 8) {
        int py = pi >> 3, px = pi & 7;
        int gy = Ty + py, gx = Tx + px;
        size_t gp = ((size_t)((b * 64 + gy) * 64 + gx)) * 256 + hb + lane;
        float q = g_Q[gp];
        // slot row/col of the window origin in the halo tile:
        // slot(dy,dx) = (cy - Ty + dy) * HALO + (cx - Tx + dx), dy,dx in [0,6]
        int pr0 = min(max(gy, 3), 60) - Ty;
        int pc0 = min(max(gx, 3), 60) - Tx;

        float sc[49];
#pragma unroll
        for (int s = 0; s < 49; s++) {
            int dy = s / 7;
            int dx = s - dy * 7;
            int p  = (pr0 + dy) * HALO + pc0 + dx;
            float v = (Ks[p * 32 + lane] + Ps[s * 32 + lane]) * q;
            v += __shfl_xor_sync(0xffffffffu, v, 16);
            v += __shfl_xor_sync(0xffffffffu, v, 8);
            v += __shfl_xor_sync(0xffffffffu, v, 4);
            v += __shfl_xor_sync(0xffffffffu, v, 2);
            v += __shfl_xor_sync(0xffffffffu, v, 1);
            sc[s] = v * scale;
        }
        float m = sc[0];
#pragma unroll
        for (int s = 1; s < 49; s++) m = fmaxf(m, sc[s]);
        float l = 0.f, acc = 0.f;
#pragma unroll
        for (int s = 0; s < 49; s++) {
            float p_ = __expf(sc[s] - m);
            l += p_;
            int dy = s / 7;
            int dx = s - dy * 7;
            int pp = (pr0 + dy) * HALO + pc0 + dx;
            acc = fmaf(p_, Vs[pp * 32 + lane], acc);
        }
        g_att[gp] = acc / (l + 1e-8f);
    }
}

// ---------------------------------------------------------------------------
extern "C" void kernel_launch(void* const* d_in, const int* in_sizes, int n_in,
                              void* d_out, int out_size)
{
    const float* x   = (const float*)d_in[0];
    const float* Wq  = (const float*)d_in[1];
    const float* Wk  = (const float*)d_in[2];
    const float* Wv  = (const float*)d_in[3];
    const float* Wo  = (const float*)d_in[4];
    const float* pos = (const float*)d_in[5];

    // 1) QKV projections (+pos epilogue on Q)
    dim3 gq(256 / GBN, NPIX / GBM, 3);
    qkv_kernel<<<gq, 256>>>(x, Wq, Wk, Wv, pos);

    // 2) Local attention
    int smem = (2 * NP * 32 + 49 * 32) * (int)sizeof(float); // 56448 B
    cudaFuncSetAttribute(attn_kernel, cudaFuncAttributeMaxDynamicSharedMemorySize, smem);
    attn_kernel<<<dim3(64, Hd, Bd), 256, smem>>>(pos);

    // 3) Output projection
    out_kernel<<<dim3(256 / GBN, NPIX / GBM, 1), 256>>>(Wo, (float*)d_out);
}

// round 2
// speedup vs baseline: 1.2984x; 1.2984x over previous
#include <cuda_runtime.h>

// Problem constants
#define Bd 4
#define Yd 64
#define Xd 64
#define Cd 256
#define Hd 8
#define Fd 32
#define NPIX (Bd*Yd*Xd)   // 16384

__device__ float g_Q[NPIX*Cd];
__device__ float g_K[NPIX*Cd];
__device__ float g_V[NPIX*Cd];
__device__ float g_att[NPIX*Cd];

// ---------------------------------------------------------------------------
// SGEMM: C[M x 256] = A[M x 256] @ B[256 x 256]; double-buffered, 8x8/thread
// BM=128, BN=128, BK=16, 256 threads
// ---------------------------------------------------------------------------
#define GBM 128
#define GBN 128
#define GBK 16

__device__ __forceinline__ void sgemm2(const float* __restrict__ A,
                                       const float* __restrict__ B,
                                       float* __restrict__ C,
                                       const float* __restrict__ pos,
                                       bool addpos)
{
    __shared__ float As[2][GBK][GBM + 4];   // +4 pad: conflict-free transpose store
    __shared__ float Bs[2][GBK][GBN];

    const int t   = threadIdx.x;
    const int m0  = blockIdx.y * GBM;
    const int n0  = blockIdx.x * GBN;
    const int tm0 = (t >> 4) << 3;
    const int tn0 = (t & 15) << 3;

    const int ar0 = t >> 2;           // 0..63
    const int akc = (t & 3) << 2;     // 0,4,8,12
    const int brow = t >> 5;          // 0..7
    const int bcol = (t & 31) << 2;   // 0..124

    float4 pa0, pa1, pb0, pb1;

    auto ldg = [&](int k0) {
        pa0 = *(const float4*)(A + (size_t)(m0 + ar0)      * 256 + k0 + akc);
        pa1 = *(const float4*)(A + (size_t)(m0 + 64 + ar0) * 256 + k0 + akc);
        pb0 = *(const float4*)(B + (size_t)(k0 + brow)     * 256 + n0 + bcol);
        pb1 = *(const float4*)(B + (size_t)(k0 + brow + 8) * 256 + n0 + bcol);
    };
    auto sts = [&](int buf) {
        As[buf][akc + 0][ar0] = pa0.x;
        As[buf][akc + 1][ar0] = pa0.y;
        As[buf][akc + 2][ar0] = pa0.z;
        As[buf][akc + 3][ar0] = pa0.w;
        As[buf][akc + 0][64 + ar0] = pa1.x;
        As[buf][akc + 1][64 + ar0] = pa1.y;
        As[buf][akc + 2][64 + ar0] = pa1.z;
        As[buf][akc + 3][64 + ar0] = pa1.w;
        *(float4*)(&Bs[buf][brow][bcol])     = pb0;
        *(float4*)(&Bs[buf][brow + 8][bcol]) = pb1;
    };

    float acc[8][8];
#pragma unroll
    for (int i = 0; i < 8; i++)
#pragma unroll
        for (int j = 0; j < 8; j++) acc[i][j] = 0.f;

    ldg(0); sts(0); __syncthreads();

    for (int kt = 0; kt < 16; kt++) {
        const int buf = kt & 1;
        const bool more = (kt < 15);
        if (more) ldg((kt + 1) << 4);
#pragma unroll
        for (int k = 0; k < GBK; k++) {
            float a[8], b[8];
            float4 a0 = *(float4*)(&As[buf][k][tm0]);
            float4 a1 = *(float4*)(&As[buf][k][tm0 + 4]);
            float4 b0 = *(float4*)(&Bs[buf][k][tn0]);
            float4 b1 = *(float4*)(&Bs[buf][k][tn0 + 4]);
            a[0]=a0.x; a[1]=a0.y; a[2]=a0.z; a[3]=a0.w;
            a[4]=a1.x; a[5]=a1.y; a[6]=a1.z; a[7]=a1.w;
            b[0]=b0.x; b[1]=b0.y; b[2]=b0.z; b[3]=b0.w;
            b[4]=b1.x; b[5]=b1.y; b[6]=b1.z; b[7]=b1.w;
#pragma unroll
            for (int i = 0; i < 8; i++)
#pragma unroll
                for (int j = 0; j < 8; j++)
                    acc[i][j] = fmaf(a[i], b[j], acc[i][j]);
        }
        if (more) { sts(buf ^ 1); __syncthreads(); }
    }

#pragma unroll
    for (int i = 0; i < 8; i++) {
        const int m = m0 + tm0 + i;
        float4 v0 = make_float4(acc[i][0], acc[i][1], acc[i][2], acc[i][3]);
        float4 v1 = make_float4(acc[i][4], acc[i][5], acc[i][6], acc[i][7]);
        if (addpos) {
            int y  = (m >> 6) & 63;
            int x  = m & 63;
            int qy = y - min(max(y, 3), 60) + 3;
            int qx = x - min(max(x, 3), 60) + 3;
            const float* pe = pos + (size_t)(qy * 7 + qx) * 256 + n0 + tn0;
            const float4 p0 = *(const float4*)(pe);
            const float4 p1 = *(const float4*)(pe + 4);
            v0.x += p0.x; v0.y += p0.y; v0.z += p0.z; v0.w += p0.w;
            v1.x += p1.x; v1.y += p1.y; v1.z += p1.z; v1.w += p1.w;
        }
        *(float4*)(C + (size_t)m * 256 + n0 + tn0)     = v0;
        *(float4*)(C + (size_t)m * 256 + n0 + tn0 + 4) = v1;
    }
}

__global__ __launch_bounds__(256) void qkv_kernel(const float* __restrict__ X,
                                                  const float* __restrict__ Wq,
                                                  const float* __restrict__ Wk,
                                                  const float* __restrict__ Wv,
                                                  const float* __restrict__ pos)
{
    int mat = blockIdx.z;
    const float* W = (mat == 0) ? Wq : ((mat == 1) ? Wk : Wv);
    float* O       = (mat == 0) ? g_Q : ((mat == 1) ? g_K : g_V);
    sgemm2(X, W, O, pos, mat == 0);
}

__global__ __launch_bounds__(256) void out_kernel(const float* __restrict__ Wo,
                                                  float* __restrict__ out)
{
    sgemm2(g_att, Wo, out, nullptr, false);
}

// ---------------------------------------------------------------------------
// Attention: thread = (pixel, head). Block = 16x8 pixel tile, 1 head, 128 thr.
// Smem f4-major so lanes read consecutive 16B -> conflict-free LDS.128.
// Softmax without max-subtraction (scores bounded) — mathematically identical.
// ---------------------------------------------------------------------------
#define TW 16
#define TH 8
#define HW 22
#define HH 14
#define NR (HW*HH)   // 308

__global__ __launch_bounds__(128) void attn_kernel(const float* __restrict__ pos)
{
    extern __shared__ float4 sm4[];
    float4* Ks4 = sm4;                    // [8][NR]
    float4* Vs4 = sm4 + 8 * NR;           // [8][NR]
    float4* Ps4 = sm4 + 16 * NR;          // [8][49]
    float4* Qs4 = sm4 + 16 * NR + 8 * 49; // [8][128]

    const int bx = blockIdx.x;            // 0..31 (8 y-tiles x 4 x-tiles)
    const int h  = blockIdx.y;
    const int b  = blockIdx.z;
    const int Ty = (bx >> 2) * TH;
    const int Tx = (bx & 3) * TW;
    const int t  = threadIdx.x;
    const int hb = h * 32;

    // K/V halo: 308 rows x 8 float4
    for (int i = t; i < NR * 8; i += 128) {
        int r  = i >> 3;
        int f4 = i & 7;
        int ry = r / HW;
        int rx = r - ry * HW;
        int gy = min(max(Ty - 3 + ry, 0), 63);
        int gx = min(max(Tx - 3 + rx, 0), 63);
        size_t off = ((size_t)(((b << 6) + gy) << 6) + gx) * 256 + hb + (f4 << 2);
        Ks4[f4 * NR + r] = *(const float4*)(g_K + off);
        Vs4[f4 * NR + r] = *(const float4*)(g_V + off);
    }
    // pos_emb slice: 49 x 8 float4
    for (int i = t; i < 49 * 8; i += 128) {
        int s  = i >> 3;
        int f4 = i & 7;
        Ps4[f4 * 49 + s] = *(const float4*)(pos + (size_t)s * 256 + hb + (f4 << 2));
    }
    // Q tile staging (coalesced)
    {
        const int py = t >> 4, px = t & 15;
        size_t off = ((size_t)(((b << 6) + Ty + py) << 6) + Tx + px) * 256 + hb;
#pragma unroll
        for (int f4 = 0; f4 < 8; f4++)
            Qs4[f4 * 128 + t] = *(const float4*)(g_Q + off + (f4 << 2));
    }
    __syncthreads();

    const int py = t >> 4, px = t & 15;
    const int gy = Ty + py, gx = Tx + px;
    const int pr0 = min(max(gy, 3), 60) - Ty;  // halo row of window start
    const int pc0 = min(max(gx, 3), 60) - Tx;  // halo col of window start

    const float scale = 0.17677669529663687f;  // 1/sqrt(32)
    float4 q[8];
#pragma unroll
    for (int f4 = 0; f4 < 8; f4++) {
        float4 v = Qs4[f4 * 128 + t];
        v.x *= scale; v.y *= scale; v.z *= scale; v.w *= scale;
        q[f4] = v;
    }

    float4 acc[8];
#pragma unroll
    for (int f4 = 0; f4 < 8; f4++) acc[f4] = make_float4(0.f, 0.f, 0.f, 0.f);
    float l = 0.f;

#pragma unroll 1
    for (int dy = 0; dy < 7; dy++) {
        const int r0 = (pr0 + dy) * HW + pc0;
        const int s0 = dy * 7;
#pragma unroll
        for (int dx = 0; dx < 7; dx++) {
            const int r = r0 + dx;
            const int s = s0 + dx;
            float4 d = make_float4(0.f, 0.f, 0.f, 0.f);
#pragma unroll
            for (int f4 = 0; f4 < 8; f4++) {
                const float4 k = Ks4[f4 * NR + r];
                const float4 p = Ps4[f4 * 49 + s];
                d.x = fmaf(q[f4].x, k.x + p.x, d.x);
                d.y = fmaf(q[f4].y, k.y + p.y, d.y);
                d.z = fmaf(q[f4].z, k.z + p.z, d.z);
                d.w = fmaf(q[f4].w, k.w + p.w, d.w);
            }
            const float sc = (d.x + d.y) + (d.z + d.w);
            const float w  = __expf(sc);
            l += w;
#pragma unroll
            for (int f4 = 0; f4 < 8; f4++) {
                const float4 v = Vs4[f4 * NR + r];
                acc[f4].x = fmaf(w, v.x, acc[f4].x);
                acc[f4].y = fmaf(w, v.y, acc[f4].y);
                acc[f4].z = fmaf(w, v.z, acc[f4].z);
                acc[f4].w = fmaf(w, v.w, acc[f4].w);
            }
        }
    }

    const float inv = __fdividef(1.f, l + 1e-8f);
    size_t off = ((size_t)(((b << 6) + gy) << 6) + gx) * 256 + hb;
#pragma unroll
    for (int f4 = 0; f4 < 8; f4++) {
        float4 o = acc[f4];
        o.x *= inv; o.y *= inv; o.z *= inv; o.w *= inv;
        *(float4*)(g_att + off + (f4 << 2)) = o;
    }
}

// ---------------------------------------------------------------------------
extern "C" void kernel_launch(void* const* d_in, const int* in_sizes, int n_in,
                              void* d_out, int out_size)
{
    const float* x   = (const float*)d_in[0];
    const float* Wq  = (const float*)d_in[1];
    const float* Wk  = (const float*)d_in[2];
    const float* Wv  = (const float*)d_in[3];
    const float* Wo  = (const float*)d_in[4];
    const float* pos = (const float*)d_in[5];

    // 1) QKV projections (+pos epilogue on Q)
    qkv_kernel<<<dim3(Cd / GBN, NPIX / GBM, 3), 256>>>(x, Wq, Wk, Wv, pos);

    // 2) Local attention
    const int smem = (16 * NR + 8 * 49 + 8 * 128) * (int)sizeof(float4); // 101504 B
    cudaFuncSetAttribute(attn_kernel, cudaFuncAttributeMaxDynamicSharedMemorySize, smem);
    attn_kernel<<<dim3(32, Hd, Bd), 128, smem>>>(pos);

    // 3) Output projection
    out_kernel<<<dim3(Cd / GBN, NPIX / GBM, 1), 256>>>(Wo, (float*)d_out);
}